// round 7
// baseline (speedup 1.0000x reference)
#include <cuda_runtime.h>

#define NB      128
#define APR     6                    // apron: stencil radius 3 + off-grid center slack 3
#define ROWS    (NB + 2*APR)         // 140
#define STRIDE  167                  // >= 140, and 167 % 32 == 7 -> bank permutation holds
#define NBLK    296                  // 2 CTAs/SM
#define NTHR    768
#define NWARP   (NTHR / 32)
// sqrt(log2(e)/2): pre-scaling coords by this makes w = ex2(-(dx^2+dy^2))
#define SQC     0.84932184f

__device__ float    g_hist[NB * NB];   // zeroed at load; re-zeroed each replay by last block
__device__ float    g_sum;
__device__ unsigned g_done;

// single-instruction exp2 (MUFU.EX2), immune to fast-math flags
__device__ __forceinline__ float ex2(float v) {
    float r;
    asm("ex2.approx.ftz.f32 %0, %1;" : "=f"(r) : "f"(v));
    return r;
}

// Elliptical stencil di^2+dj^2 <= 10 (37 cells), split so each ATOMS is conflict-free:
// set1 (32 cells): keys (7*di+dj) mod 32 cover banks 0..31 exactly once (STRIDE%32==7).
__constant__ signed char C1I[32] = {-3,-3,-3, -2,-2,-2,-2,-2, -1,-1,-1,-1,-1,-1,-1,
                                     0,0,0,0,0,0,0, 1,1,1,1,1,1, 2,2,2, 3};
__constant__ signed char C1J[32] = {-1,0,1, -2,-1,0,1,2, -3,-2,-1,0,1,2,3,
                                    -3,-2,-1,0,1,2,3, -3,-2,-1,0,1,2, -1,0,1, 0};
// set2 (5 cells, lanes 0..4): distinct banks.
__constant__ signed char C2I[5] = {1, 2, 2, 3, 3};
__constant__ signed char C2J[5] = {3,-2, 2,-1, 1};

__global__ void __launch_bounds__(NTHR, 2)
accum_kernel(const float* __restrict__ x,
             const float* __restrict__ ex,
             const float* __restrict__ ey,
             float* __restrict__ out,
             int n) {
    extern __shared__ float sh[];   // ROWS * STRIDE floats (incl. apron)
    __shared__ float blk_sum;
    __shared__ int   s_last;
    for (int i = threadIdx.x; i < ROWS * STRIDE; i += NTHR) sh[i] = 0.0f;
    if (threadIdx.x == 0) { blk_sum = 0.0f; s_last = 0; }
    __syncthreads();

    const float bwx = ex[1] - ex[0];
    const float bwy = ey[1] - ey[0];
    const float inv_bwx = 1.0f / bwx;
    const float inv_bwy = 1.0f / bwy;
    const float c0x = 0.5f * (ex[0] + ex[1]);
    const float c0y = 0.5f * (ey[0] + ey[1]);

    const int lane = threadIdx.x & 31;
    const int gw   = blockIdx.x * NWARP + (threadIdx.x >> 5);
    const int nw   = NBLK * NWARP;

    // per-lane stencil constants, pre-scaled by SQC
    const float f1i = SQC * (float)C1I[lane], f1j = SQC * (float)C1J[lane];
    const int   off1 = C1I[lane] * STRIDE + C1J[lane];
    const int   l2 = (lane < 5) ? lane : 0;
    const float f2i = SQC * (float)C2I[l2], f2j = SQC * (float)C2J[l2];
    const int   off2 = C2I[l2] * STRIDE + C2J[l2];
    const bool  has2 = (lane < 5);

    for (int p0 = gw * 32; p0 < n; p0 += nw * 32) {
        int pi = p0 + lane;
        // ---- per-lane precompute for own point ----
        int   base = 0;
        float fxs = 0.0f, fys = 0.0f;
        bool  valid = (pi < n);
        if (valid) {
            float2 pt = __ldg((const float2*)(x + pi * 6));   // dims 0,1; 24B row stride
            float ux = (pt.x - c0x) * inv_bwx;   // bin-center units
            float uy = (pt.y - c0y) * inv_bwy;
            float rx = rintf(ux), ry = rintf(uy);
            int ix0 = (int)rx, iy0 = (int)ry;
            fxs = (ux - rx) * SQC;               // scaled frac in [-0.42, 0.42]
            fys = (uy - ry) * SQC;
            // points with ix0/iy0 outside [-3,130] touch no in-range bin
            valid = ((unsigned)(ix0 + 3) <= 133u) && ((unsigned)(iy0 + 3) <= 133u);
            base = (ix0 + APR) * STRIDE + (iy0 + APR);
        }
        unsigned vm = __ballot_sync(0xffffffffu, valid);

        #pragma unroll 4
        for (int k = 0; k < 32; ++k) {
            if (!((vm >> k) & 1u)) continue;     // warp-uniform, rarely taken
            int   bk  = __shfl_sync(0xffffffffu, base, k);
            float fxk = __shfl_sync(0xffffffffu, fxs, k);
            float fyk = __shfl_sync(0xffffffffu, fys, k);
            // cell 1: all 32 lanes, banks are a permutation -> conflict-free ATOMS
            float dx = fxk - f1i, dy = fyk - f1j;
            float w  = ex2(fmaf(dx, -dx, -dy * dy));   // e^{-1/2(di^2+dj^2)} after scaling
            atomicAdd(&sh[bk + off1], w);
            // cell 2: lanes 0..4, distinct banks
            float dx2 = fxk - f2i, dy2 = fyk - f2j;
            float w2  = ex2(fmaf(dx2, -dx2, -dy2 * dy2));
            if (has2) atomicAdd(&sh[bk + off2], w2);
        }
    }

    __syncthreads();
    // flush interior of block-private hist to global; accumulate block total
    float my_sum = 0.0f;
    for (int i = threadIdx.x; i < NB * NB; i += NTHR) {
        int r = i >> 7, c = i & (NB - 1);
        float v = sh[(r + APR) * STRIDE + (c + APR)];
        my_sum += v;
        if (v != 0.0f) atomicAdd(&g_hist[i], v);
    }
    #pragma unroll
    for (int off = 16; off > 0; off >>= 1)
        my_sum += __shfl_down_sync(0xffffffffu, my_sum, off);
    if ((threadIdx.x & 31) == 0) atomicAdd(&blk_sum, my_sum);
    __syncthreads();

    // last-block epilogue: normalize + reset (replaces two extra kernel launches)
    if (threadIdx.x == 0) {
        atomicAdd(&g_sum, blk_sum);
        __threadfence();
        unsigned t = atomicAdd(&g_done, 1u);
        s_last = (t == (unsigned)(NBLK - 1));
    }
    __syncthreads();
    if (s_last) {
        float scale = 1.0f / (g_sum * bwx * bwy);
        for (int i = threadIdx.x; i < NB * NB; i += NTHR) {
            out[i] = g_hist[i] * scale;
            g_hist[i] = 0.0f;                   // reset for next graph replay
        }
        if (threadIdx.x == 0) { g_sum = 0.0f; g_done = 0u; }
    }
}

extern "C" void kernel_launch(void* const* d_in, const int* in_sizes, int n_in,
                              void* d_out, int out_size) {
    const float* x  = (const float*)d_in[0];
    const float* ex = (const float*)d_in[1];
    const float* ey = (const float*)d_in[2];
    int n = in_sizes[0] / 6;

    const int SMEM = ROWS * STRIDE * (int)sizeof(float);   // 93520 B
    cudaFuncSetAttribute(accum_kernel, cudaFuncAttributeMaxDynamicSharedMemorySize, SMEM);

    accum_kernel<<<NBLK, NTHR, SMEM>>>(x, ex, ey, (float*)d_out, n);
}

// round 8
// speedup vs baseline: 1.7870x; 1.7870x over previous
#include <cuda_runtime.h>

#define NB      128
#define APR     6                    // apron: stencil radius 3 + off-grid center slack 3
#define ROWS    (NB + 2*APR)         // 140
#define STRIDE  167                  // >= 140, and 167 % 32 == 7 -> bank permutation holds
#define NBLK    296                  // 2 CTAs/SM
#define NTHR    768
#define NWARP   (NTHR / 32)
// sqrt(log2(e)/2): pre-scaling coords by this makes w = ex2(-(dx^2+dy^2))
#define SQC     0.84932184f

__device__ float g_hist[NB * NB];   // zeroed at load; re-zeroed by normalize each replay
__device__ float g_sum;
__device__ float g_scale;

// single-instruction exp2 (MUFU.EX2), immune to fast-math flags
__device__ __forceinline__ float ex2(float v) {
    float r;
    asm("ex2.approx.ftz.f32 %0, %1;" : "=f"(r) : "f"(v));
    return r;
}

// Elliptical stencil di^2+dj^2 <= 10 (37 cells), split so each ATOMS is conflict-free:
// set1 (32 cells): keys (7*di+dj) mod 32 cover banks 0..31 exactly once (STRIDE%32==7).
__constant__ signed char C1I[32] = {-3,-3,-3, -2,-2,-2,-2,-2, -1,-1,-1,-1,-1,-1,-1,
                                     0,0,0,0,0,0,0, 1,1,1,1,1,1, 2,2,2, 3};
__constant__ signed char C1J[32] = {-1,0,1, -2,-1,0,1,2, -3,-2,-1,0,1,2,3,
                                    -3,-2,-1,0,1,2,3, -3,-2,-1,0,1,2, -1,0,1, 0};
// set2 (5 cells, lanes 0..4): distinct banks.
__constant__ signed char C2I[5] = {1, 2, 2, 3, 3};
__constant__ signed char C2J[5] = {3,-2, 2,-1, 1};

__global__ void __launch_bounds__(NTHR, 2)
accum_kernel(const float* __restrict__ x,
             const float* __restrict__ ex,
             const float* __restrict__ ey,
             int n) {
    extern __shared__ float sh[];   // ROWS * STRIDE floats (incl. apron)
    __shared__ float blk_sum;
    for (int i = threadIdx.x; i < ROWS * STRIDE; i += NTHR) sh[i] = 0.0f;
    if (threadIdx.x == 0) blk_sum = 0.0f;
    __syncthreads();

    const float bwx = ex[1] - ex[0];
    const float bwy = ey[1] - ey[0];
    const float inv_bwx = 1.0f / bwx;
    const float inv_bwy = 1.0f / bwy;
    const float c0x = 0.5f * (ex[0] + ex[1]);
    const float c0y = 0.5f * (ey[0] + ey[1]);

    const int lane = threadIdx.x & 31;
    const int gw   = blockIdx.x * NWARP + (threadIdx.x >> 5);
    const int nw   = NBLK * NWARP;

    // per-lane stencil constants, pre-scaled by SQC
    const float f1i = SQC * (float)C1I[lane], f1j = SQC * (float)C1J[lane];
    const int   off1 = C1I[lane] * STRIDE + C1J[lane];
    const int   l2 = (lane < 5) ? lane : 0;
    const float f2i = SQC * (float)C2I[l2], f2j = SQC * (float)C2J[l2];
    const int   off2 = C2I[l2] * STRIDE + C2J[l2];
    const bool  has2 = (lane < 5);

    for (int p0 = gw * 32; p0 < n; p0 += nw * 32) {
        int pi = p0 + lane;
        // ---- per-lane precompute for own point ----
        int   base = 0;
        float fxs = 0.0f, fys = 0.0f;
        bool  valid = (pi < n);
        if (valid) {
            float2 pt = __ldg((const float2*)(x + pi * 6));   // dims 0,1; 24B row stride
            float ux = (pt.x - c0x) * inv_bwx;   // bin-center units
            float uy = (pt.y - c0y) * inv_bwy;
            float rx = rintf(ux), ry = rintf(uy);
            int ix0 = (int)rx, iy0 = (int)ry;
            fxs = (ux - rx) * SQC;               // scaled frac in [-0.42, 0.42]
            fys = (uy - ry) * SQC;
            // points with ix0/iy0 outside [-3,130] touch no in-range bin
            valid = ((unsigned)(ix0 + 3) <= 133u) && ((unsigned)(iy0 + 3) <= 133u);
            base = (ix0 + APR) * STRIDE + (iy0 + APR);
        }
        unsigned vm = __ballot_sync(0xffffffffu, valid);

        #pragma unroll 4
        for (int k = 0; k < 32; ++k) {
            if (!((vm >> k) & 1u)) continue;     // warp-uniform, rarely taken
            int   bk  = __shfl_sync(0xffffffffu, base, k);
            float fxk = __shfl_sync(0xffffffffu, fxs, k);
            float fyk = __shfl_sync(0xffffffffu, fys, k);
            // cell 1: all 32 lanes, banks are a permutation -> conflict-free ATOMS
            float dx = fxk - f1i, dy = fyk - f1j;
            float w  = ex2(fmaf(dx, -dx, -dy * dy));   // e^{-(di^2+dj^2)/2} after scaling
            atomicAdd(&sh[bk + off1], w);
            // cell 2: lanes 0..4, distinct banks
            float dx2 = fxk - f2i, dy2 = fyk - f2j;
            float w2  = ex2(fmaf(dx2, -dx2, -dy2 * dy2));
            if (has2) atomicAdd(&sh[bk + off2], w2);
        }
    }

    __syncthreads();
    // flush interior of block-private hist to global; accumulate block total
    float my_sum = 0.0f;
    for (int i = threadIdx.x; i < NB * NB; i += NTHR) {
        int r = i >> 7, c = i & (NB - 1);
        float v = sh[(r + APR) * STRIDE + (c + APR)];
        my_sum += v;
        if (v != 0.0f) atomicAdd(&g_hist[i], v);
    }
    #pragma unroll
    for (int off = 16; off > 0; off >>= 1)
        my_sum += __shfl_down_sync(0xffffffffu, my_sum, off);
    if ((threadIdx.x & 31) == 0) atomicAdd(&blk_sum, my_sum);
    __syncthreads();
    if (threadIdx.x == 0) atomicAdd(&g_sum, blk_sum);
}

__global__ void scale_kernel(const float* __restrict__ ex,
                             const float* __restrict__ ey) {
    float bwx = ex[1] - ex[0];
    float bwy = ey[1] - ey[0];
    g_scale = 1.0f / (g_sum * bwx * bwy);
    g_sum = 0.0f;   // reset for next graph replay
}

__global__ void normalize_kernel(float* __restrict__ out) {
    int i = blockIdx.x * blockDim.x + threadIdx.x;   // 64 CTAs x 256 = NB*NB
    out[i] = g_hist[i] * g_scale;
    g_hist[i] = 0.0f;   // reset for next graph replay
}

extern "C" void kernel_launch(void* const* d_in, const int* in_sizes, int n_in,
                              void* d_out, int out_size) {
    const float* x  = (const float*)d_in[0];
    const float* ex = (const float*)d_in[1];
    const float* ey = (const float*)d_in[2];
    int n = in_sizes[0] / 6;

    const int SMEM = ROWS * STRIDE * (int)sizeof(float);   // 93520 B
    cudaFuncSetAttribute(accum_kernel, cudaFuncAttributeMaxDynamicSharedMemorySize, SMEM);

    accum_kernel<<<NBLK, NTHR, SMEM>>>(x, ex, ey, n);
    scale_kernel<<<1, 1>>>(ex, ey);
    normalize_kernel<<<(NB * NB) / 256, 256>>>((float*)d_out);
}

// round 9
// speedup vs baseline: 1.9713x; 1.1032x over previous
#include <cuda_runtime.h>

#define NB      128
#define APR     6                    // apron: stencil radius 3 + off-grid center slack 3
#define ROWS    (NB + 2*APR)         // 140
#define STRIDE  167                  // >= 140, and 167 % 32 == 7 -> near-perfect bank spread
#define NBLK    296                  // 2 CTAs/SM
#define NTHR    768
#define NWARP   (NTHR / 32)
// sqrt(log2(e)/2): pre-scaling coords by this makes w = ex2(-(dx^2+dy^2))
#define SQC     0.84932184f

__device__ float g_hist[NB * NB];   // zeroed at load; re-zeroed by normalize each replay
__device__ float g_sum;
__device__ float g_scale;

// single-instruction exp2 (MUFU.EX2), immune to fast-math flags
__device__ __forceinline__ float ex2(float v) {
    float r;
    asm("ex2.approx.ftz.f32 %0, %1;" : "=f"(r) : "f"(v));
    return r;
}

// Elliptical stencil di^2+dj^2 <= 9: 29 cells, one per lane (lanes 29..31 idle).
// Bank keys (7*di+dj) mod 32: 28 distinct + one 2-way pair -> ~conflict-free ATOMS.
__constant__ signed char C1I[32] = {-3, -2,-2,-2,-2,-2, -1,-1,-1,-1,-1,
                                     0,0,0,0,0,0,0, 1,1,1,1,1, 2,2,2,2,2, 3, 0,0,0};
__constant__ signed char C1J[32] = { 0, -2,-1,0,1,2, -2,-1,0,1,2,
                                    -3,-2,-1,0,1,2,3, -2,-1,0,1,2, -2,-1,0,1,2, 0, 0,0,0};

__global__ void __launch_bounds__(NTHR, 2)
accum_kernel(const float* __restrict__ x,
             const float* __restrict__ ex,
             const float* __restrict__ ey,
             int n) {
    extern __shared__ float sh[];   // ROWS * STRIDE floats (incl. apron)
    __shared__ float blk_sum;
    for (int i = threadIdx.x; i < ROWS * STRIDE; i += NTHR) sh[i] = 0.0f;
    if (threadIdx.x == 0) blk_sum = 0.0f;
    __syncthreads();

    const float bwx = ex[1] - ex[0];
    const float bwy = ey[1] - ey[0];
    const float inv_bwx = 1.0f / bwx;
    const float inv_bwy = 1.0f / bwy;
    const float c0x = 0.5f * (ex[0] + ex[1]);
    const float c0y = 0.5f * (ey[0] + ey[1]);

    const int lane = threadIdx.x & 31;
    const int gw   = blockIdx.x * NWARP + (threadIdx.x >> 5);
    const int nw   = NBLK * NWARP;

    // per-lane stencil constants, pre-scaled by SQC
    const float f1i = SQC * (float)C1I[lane], f1j = SQC * (float)C1J[lane];
    const int   off1 = C1I[lane] * STRIDE + C1J[lane];
    const bool  active = (lane < 29);
    const int   SAFE_BASE = APR * STRIDE + APR;   // dump site for zero-weight adds

    for (int p0 = gw * 32; p0 < n; p0 += nw * 32) {
        int pi = p0 + lane;
        // ---- per-lane precompute for own point (branch-free invalid handling) ----
        int   base = SAFE_BASE;
        float fxs = 1.0e10f, fys = 1.0e10f;      // -> ex2(-inf) = 0, harmless add
        if (pi < n) {
            float2 pt = __ldg((const float2*)(x + pi * 6));   // dims 0,1; 24B row stride
            float ux = (pt.x - c0x) * inv_bwx;   // bin-center units
            float uy = (pt.y - c0y) * inv_bwy;
            float rx = rintf(ux), ry = rintf(uy);
            int ix0 = (int)rx, iy0 = (int)ry;
            if (((unsigned)(ix0 + 3) <= 133u) && ((unsigned)(iy0 + 3) <= 133u)) {
                fxs = (ux - rx) * SQC;           // scaled frac in [-0.42, 0.42]
                fys = (uy - ry) * SQC;
                base = (ix0 + APR) * STRIDE + (iy0 + APR);
            }
        }

        #pragma unroll 8
        for (int k = 0; k < 32; ++k) {
            int   bk  = __shfl_sync(0xffffffffu, base, k);
            float fxk = __shfl_sync(0xffffffffu, fxs, k);
            float fyk = __shfl_sync(0xffffffffu, fys, k);
            float dx = fxk - f1i, dy = fyk - f1j;
            float w  = ex2(fmaf(dx, -dx, -dy * dy));   // e^{-(di^2+dj^2)/2} after scaling
            if (active) atomicAdd(&sh[bk + off1], w);  // single warp-wide ATOMS
        }
    }

    __syncthreads();
    // flush interior of block-private hist to global; accumulate block total
    float my_sum = 0.0f;
    for (int i = threadIdx.x; i < NB * NB; i += NTHR) {
        int r = i >> 7, c = i & (NB - 1);
        float v = sh[(r + APR) * STRIDE + (c + APR)];
        my_sum += v;
        if (v != 0.0f) atomicAdd(&g_hist[i], v);
    }
    #pragma unroll
    for (int off = 16; off > 0; off >>= 1)
        my_sum += __shfl_down_sync(0xffffffffu, my_sum, off);
    if ((threadIdx.x & 31) == 0) atomicAdd(&blk_sum, my_sum);
    __syncthreads();
    if (threadIdx.x == 0) atomicAdd(&g_sum, blk_sum);
}

__global__ void scale_kernel(const float* __restrict__ ex,
                             const float* __restrict__ ey) {
    float bwx = ex[1] - ex[0];
    float bwy = ey[1] - ey[0];
    g_scale = 1.0f / (g_sum * bwx * bwy);
    g_sum = 0.0f;   // reset for next graph replay
}

__global__ void normalize_kernel(float* __restrict__ out) {
    int i = blockIdx.x * blockDim.x + threadIdx.x;   // 64 CTAs x 256 = NB*NB
    out[i] = g_hist[i] * g_scale;
    g_hist[i] = 0.0f;   // reset for next graph replay
}

extern "C" void kernel_launch(void* const* d_in, const int* in_sizes, int n_in,
                              void* d_out, int out_size) {
    const float* x  = (const float*)d_in[0];
    const float* ex = (const float*)d_in[1];
    const float* ey = (const float*)d_in[2];
    int n = in_sizes[0] / 6;

    const int SMEM = ROWS * STRIDE * (int)sizeof(float);   // 93520 B
    cudaFuncSetAttribute(accum_kernel, cudaFuncAttributeMaxDynamicSharedMemorySize, SMEM);

    accum_kernel<<<NBLK, NTHR, SMEM>>>(x, ex, ey, n);
    scale_kernel<<<1, 1>>>(ex, ey);
    normalize_kernel<<<(NB * NB) / 256, 256>>>((float*)d_out);
}

// round 10
// speedup vs baseline: 3.1463x; 1.5960x over previous
#include <cuda_runtime.h>

#define NB    128
#define DR    144            // fine deposit grid rows (x), with apron
#define DC    144            // fine deposit grid cols (y)
#define OFFS  7              // bin index m  ->  deposit index m + OFFS
#define NTAP  11             // conv radius 5, Gaussian var = 3/4
#define NBLK  148            // 1 CTA/SM
#define NTHR  1024

__device__ float g_fine[DR * DC];   // accumulated; zeroed at load, re-zeroed by conv2
__device__ float g_T[DR * NB];      // y-convolved intermediate (overwritten each replay)
__device__ float g_hist[NB * NB];   // unnormalized result (overwritten each replay)
__device__ float g_sum;             // accumulated; reset by next accum

// Gaussian taps, variance 3/4: w[d] = exp(-(d-5)^2 * 2/3)
__constant__ float W[NTAP] = {
    5.77776e-8f, 2.33093e-5f, 2.47875e-3f, 6.94835e-2f, 5.13417e-1f,
    1.0f,
    5.13417e-1f, 6.94835e-2f, 2.47875e-3f, 2.33093e-5f, 5.77776e-8f
};

__global__ void __launch_bounds__(NTHR, 1)
accum_kernel(const float* __restrict__ x,
             const float* __restrict__ ex,
             const float* __restrict__ ey,
             int n) {
    extern __shared__ float D[];    // DR * DC floats
    if (blockIdx.x == 0 && threadIdx.x == 0) g_sum = 0.0f;   // reset for this replay
    for (int k = threadIdx.x; k < DR * DC; k += NTHR) D[k] = 0.0f;
    __syncthreads();

    const float bwx = ex[1] - ex[0];
    const float bwy = ey[1] - ey[0];
    const float inv_bwx = 1.0f / bwx;
    const float inv_bwy = 1.0f / bwy;
    const float c0x = 0.5f * (ex[0] + ex[1]);
    const float c0y = 0.5f * (ey[0] + ey[1]);

    for (int p = blockIdx.x * NTHR + threadIdx.x; p < n; p += NBLK * NTHR) {
        float2 pt = __ldg((const float2*)(x + p * 6));   // dims 0,1; 24B row stride
        float ux = (pt.x - c0x) * inv_bwx;   // bin-center units
        float uy = (pt.y - c0y) * inv_bwy;
        float rx = rintf(ux), ry = rintf(uy);
        int mx = (int)rx, my = (int)ry;
        // points outside deposit window contribute < 1e-7 to any bin
        if (((unsigned)(mx + 6) > 139u) | ((unsigned)(my + 6) > 139u)) continue;
        float tx = ux - rx, ty = uy - ry;    // in [-0.5, 0.5]
        // TSC (quadratic) weights: preserve moments 0,1; cloud variance = 1/4 exactly
        float am = 0.5f - tx, ap = 0.5f + tx;
        float wx0 = 0.5f * am * am, wx2 = 0.5f * ap * ap, wx1 = 0.75f - tx * tx;
        float bm = 0.5f - ty, bp = 0.5f + ty;
        float wy0 = 0.5f * bm * bm, wy2 = 0.5f * bp * bp, wy1 = 0.75f - ty * ty;
        float* base = &D[(mx + OFFS - 1) * DC + (my + OFFS - 1)];
        atomicAdd(base,              wx0 * wy0);
        atomicAdd(base + 1,          wx0 * wy1);
        atomicAdd(base + 2,          wx0 * wy2);
        atomicAdd(base + DC,         wx1 * wy0);
        atomicAdd(base + DC + 1,     wx1 * wy1);
        atomicAdd(base + DC + 2,     wx1 * wy2);
        atomicAdd(base + 2 * DC,     wx2 * wy0);
        atomicAdd(base + 2 * DC + 1, wx2 * wy1);
        atomicAdd(base + 2 * DC + 2, wx2 * wy2);
    }

    __syncthreads();
    for (int k = threadIdx.x; k < DR * DC; k += NTHR) {
        float v = D[k];
        if (v != 0.0f) atomicAdd(&g_fine[k], v);
    }
}

// y-direction convolution: T[i][j] = sum_d W[d] * F[i][j+d+2]
__global__ void conv1_kernel() {
    int i = blockIdx.x;            // 0..DR-1
    int j = threadIdx.x;           // 0..NB-1
    const float* row = &g_fine[i * DC];
    float s = 0.0f;
    #pragma unroll
    for (int d = 0; d < NTAP; ++d) s = fmaf(W[d], row[j + d + 2], s);
    g_T[i * NB + j] = s;
}

// x-direction convolution + global sum + reset of g_fine
__global__ void conv2_kernel() {
    int idx = blockIdx.x * 256 + threadIdx.x;    // 64 x 256 = NB*NB
    int i = idx >> 7, j = idx & (NB - 1);
    float s = 0.0f;
    #pragma unroll
    for (int d = 0; d < NTAP; ++d) s = fmaf(W[d], g_T[(i + d + 2) * NB + j], s);
    g_hist[idx] = s;
    // block-reduce s into g_sum
    float v = s;
    #pragma unroll
    for (int o = 16; o > 0; o >>= 1) v += __shfl_down_sync(0xffffffffu, v, o);
    __shared__ float red[8];
    if ((threadIdx.x & 31) == 0) red[threadIdx.x >> 5] = v;
    __syncthreads();
    if (threadIdx.x < 8) {
        float t = red[threadIdx.x];
        #pragma unroll
        for (int o = 4; o > 0; o >>= 1) t += __shfl_down_sync(0x000000ffu, t, o);
        if (threadIdx.x == 0) atomicAdd(&g_sum, t);
    }
    // zero g_fine for the next replay (conv1 already consumed it)
    for (int k = idx; k < DR * DC; k += NB * NB) g_fine[k] = 0.0f;
}

__global__ void normalize_kernel(float* __restrict__ out,
                                 const float* __restrict__ ex,
                                 const float* __restrict__ ey) {
    int idx = blockIdx.x * 256 + threadIdx.x;
    float bwx = ex[1] - ex[0];
    float bwy = ey[1] - ey[0];
    out[idx] = g_hist[idx] / (g_sum * bwx * bwy);
}

extern "C" void kernel_launch(void* const* d_in, const int* in_sizes, int n_in,
                              void* d_out, int out_size) {
    const float* x  = (const float*)d_in[0];
    const float* ex = (const float*)d_in[1];
    const float* ey = (const float*)d_in[2];
    int n = in_sizes[0] / 6;

    const int SMEM = DR * DC * (int)sizeof(float);   // 82944 B
    cudaFuncSetAttribute(accum_kernel, cudaFuncAttributeMaxDynamicSharedMemorySize, SMEM);

    accum_kernel<<<NBLK, NTHR, SMEM>>>(x, ex, ey, n);
    conv1_kernel<<<DR, NB>>>();
    conv2_kernel<<<(NB * NB) / 256, 256>>>();
    normalize_kernel<<<(NB * NB) / 256, 256>>>((float*)d_out, ex, ey);
}